// round 12
// baseline (speedup 1.0000x reference)
#include <cuda_runtime.h>
#include <cuda_bf16.h>
#include <math.h>
#include <stdint.h>

// ---------------- problem constants ----------------
#define BC    32
#define NSEQ  1024
#define DMODEL 256
#define NHEAD 8
#define DHEAD 32
#define HID   768
#define NEDGE 8192
#define LLOG  256
#define NTOK  (BC*NSEQ)   // 32768
#define NTOKL (BC*LLOG)   // 8192
#define WTOT  2031616     // total weight elements

// ---------------- scratch (__device__ globals; no allocs) ----------------
__device__ float g_a   [NTOK*DMODEL];
__device__ float g_x2  [NTOK*DMODEL];
__device__ float g_x3  [NTOK*DMODEL];
__device__ float g_l   [NTOKL*DMODEL];
__device__ float g_l2  [NTOKL*DMODEL];
__device__ int   g_start[LLOG+1];
__device__ int   g_order[NEDGE];
__device__ __nv_bfloat16 g_xnh[NTOK*DMODEL], g_xnl[NTOK*DMODEL];
__device__ __nv_bfloat16 g_qkvh[NTOK*HID],  g_qkvl[NTOK*HID];
__device__ __nv_bfloat16 g_t1h[NTOK*HID],   g_t1l[NTOK*HID];
__device__ __nv_bfloat16 g_aoh[NTOK*DMODEL], g_aol[NTOK*DMODEL];
__device__ __nv_bfloat16 g_whi[WTOT], g_wlo[WTOT];

// ================= mma helpers =================
__device__ __forceinline__ uint32_t smem_u32(const void* p) {
    uint32_t a;
    asm("{ .reg .u64 t; cvta.to.shared.u64 t, %1; cvt.u32.u64 %0, t; }"
        : "=r"(a) : "l"(p));
    return a;
}
__device__ __forceinline__ void ldsm4(uint32_t addr, uint32_t& r0, uint32_t& r1,
                                      uint32_t& r2, uint32_t& r3) {
    asm volatile("ldmatrix.sync.aligned.m8n8.x4.shared.b16 {%0,%1,%2,%3}, [%4];"
                 : "=r"(r0), "=r"(r1), "=r"(r2), "=r"(r3) : "r"(addr));
}
__device__ __forceinline__ void ldsm4t(uint32_t addr, uint32_t& r0, uint32_t& r1,
                                       uint32_t& r2, uint32_t& r3) {
    asm volatile("ldmatrix.sync.aligned.m8n8.x4.trans.shared.b16 {%0,%1,%2,%3}, [%4];"
                 : "=r"(r0), "=r"(r1), "=r"(r2), "=r"(r3) : "r"(addr));
}
__device__ __forceinline__ void mma16816(float* d, uint32_t a0, uint32_t a1,
                                         uint32_t a2, uint32_t a3,
                                         uint32_t b0, uint32_t b1) {
    asm volatile(
        "mma.sync.aligned.m16n8k16.row.col.f32.bf16.bf16.f32 "
        "{%0,%1,%2,%3}, {%4,%5,%6,%7}, {%8,%9}, {%0,%1,%2,%3};"
        : "+f"(d[0]), "+f"(d[1]), "+f"(d[2]), "+f"(d[3])
        : "r"(a0), "r"(a1), "r"(a2), "r"(a3), "r"(b0), "r"(b1));
}
__device__ __forceinline__ uint32_t packbf(float x, float y) {
    __nv_bfloat162 h = __floats2bfloat162_rn(x, y);
    return *(uint32_t*)&h;
}
__device__ __forceinline__ void cpasync16(uint32_t saddr, const void* g) {
    asm volatile("cp.async.cg.shared.global [%0], [%1], 16;" :: "r"(saddr), "l"(g));
}
__device__ __forceinline__ void cpcommit() {
    asm volatile("cp.async.commit_group;");
}

// ---------------- batched weight split (non-interleaved regions) ----------
// regions: inproj(768x256), out(256x256), fw2, dw2, lw2 (256x768 each)
__global__ __launch_bounds__(256) void wconv_all_kernel(
    const float* __restrict__ s0, const float* __restrict__ s1,
    const float* __restrict__ s2, const float* __restrict__ s3,
    const float* __restrict__ s4,
    __nv_bfloat16* __restrict__ dh, __nv_bfloat16* __restrict__ dl)
{
    int i = blockIdx.x*256 + threadIdx.x;          // float4 index
    const int B0=49152, B1=65536, B2=114688, B3=163840, B4=212992;
    if (i >= B4) return;
    const float* src; int base;
    if      (i < B0) { src = s0; base = 0;  }
    else if (i < B1) { src = s1; base = B0; }
    else if (i < B2) { src = s2; base = B1; }
    else if (i < B3) { src = s3; base = B2; }
    else             { src = s4; base = B3; }
    float4 v = ((const float4*)src)[i - base];
    float h0=__bfloat162float(__float2bfloat16_rn(v.x));
    float h1=__bfloat162float(__float2bfloat16_rn(v.y));
    float h2=__bfloat162float(__float2bfloat16_rn(v.z));
    float h3=__bfloat162float(__float2bfloat16_rn(v.w));
    ((uint2*)dh)[i] = make_uint2(packbf(h0,h1), packbf(h2,h3));
    ((uint2*)dl)[i] = make_uint2(packbf(v.x-h0,v.y-h1), packbf(v.z-h2,v.w-h3));
}

// ---------------- interleaved w1/w3 split: dest row 2i = w1 row i, 2i+1 = w3 row i
__global__ __launch_bounds__(256) void wconv_pair_kernel(
    const float* __restrict__ w1, const float* __restrict__ w3,
    __nv_bfloat16* __restrict__ dh, __nv_bfloat16* __restrict__ dl)
{
    int i = blockIdx.x*256 + threadIdx.x;          // float4 idx < 98304
    if (i >= 98304) return;
    int e = i*4;
    int drow = e >> 8;                              // 0..1535
    int col  = e & 255;
    const float* src = (drow & 1) ? w3 : w1;
    float4 v = *(const float4*)(src + (size_t)(drow >> 1)*256 + col);
    float h0=__bfloat162float(__float2bfloat16_rn(v.x));
    float h1=__bfloat162float(__float2bfloat16_rn(v.y));
    float h2=__bfloat162float(__float2bfloat16_rn(v.z));
    float h3=__bfloat162float(__float2bfloat16_rn(v.w));
    ((uint2*)dh)[i] = make_uint2(packbf(h0,h1), packbf(h2,h3));
    ((uint2*)dl)[i] = make_uint2(packbf(v.x-h0,v.y-h1), packbf(v.z-h2,v.w-h3));
}

// ---------------- bf16 GEMM: C[M,N] = (Ah+Al)(Wh+Wl)^T 3-term ----------
// CTA 128x128, BK=32, 256 threads (2x4 warps, warp tile 64x32).
// EPI: 0 fp32(+bias); 1 fp32(+bias+resid); 2 fp32 tanh(+bias+resid);
//      3 bf16 hi/lo (+bias); 4 fused swiglu over interleaved w1/w3 cols -> bf16 hi/lo N/2
#define BGS 40
#define BARR (128*BGS)
#define BBUFE (4*BARR)
#define BG_SMEM (2*BBUFE*2)

template<int EPI>
__global__ __launch_bounds__(256) void bgemm_kernel(
    const __nv_bfloat16* __restrict__ Ah, const __nv_bfloat16* __restrict__ Al,
    const __nv_bfloat16* __restrict__ Wh, const __nv_bfloat16* __restrict__ Wl,
    const float* __restrict__ bias, const float* __restrict__ resid,
    float* __restrict__ C, __nv_bfloat16* __restrict__ Ch,
    __nv_bfloat16* __restrict__ Cl, int M, int Nn, int K)
{
    extern __shared__ __nv_bfloat16 sm[];
    const int t = threadIdx.x, lane = t & 31, wid = t >> 5;
    const int wm = wid >> 2, wn = wid & 3;
    const int bm = blockIdx.y * 128, bn = blockIdx.x * 128;
    const uint32_t sbase = smem_u32(sm);
    const int nc = K / 32;

    float acc[4][4][4];
#pragma unroll
    for (int i=0;i<4;i++)
#pragma unroll
        for (int j=0;j<4;j++)
#pragma unroll
            for (int e=0;e<4;e++) acc[i][j][e]=0.f;

    const int lrow = t >> 2, lcol8 = (t & 3) * 8;
    const __nv_bfloat16* pAh0 = Ah + (size_t)(bm + lrow)*K + lcol8;
    const __nv_bfloat16* pAl0 = Al + (size_t)(bm + lrow)*K + lcol8;
    const __nv_bfloat16* pWh0 = Wh + (size_t)(bn + lrow)*K + lcol8;
    const __nv_bfloat16* pWl0 = Wl + (size_t)(bn + lrow)*K + lcol8;
    const size_t rstep = (size_t)64*K;
    const uint32_t s0 = sbase + (uint32_t)(lrow*BGS + lcol8)*2;
    const uint32_t s1 = sbase + (uint32_t)((lrow+64)*BGS + lcol8)*2;

    auto issue = [&](int c) {
        uint32_t bs = (uint32_t)(c & 1)*(BBUFE*2);
        int off = c*32;
        cpasync16(bs + s0 + 0*BARR*2, pAh0 + off);
        cpasync16(bs + s1 + 0*BARR*2, pAh0 + rstep + off);
        cpasync16(bs + s0 + 1*BARR*2, pAl0 + off);
        cpasync16(bs + s1 + 1*BARR*2, pAl0 + rstep + off);
        cpasync16(bs + s0 + 2*BARR*2, pWh0 + off);
        cpasync16(bs + s1 + 2*BARR*2, pWh0 + rstep + off);
        cpasync16(bs + s0 + 3*BARR*2, pWl0 + off);
        cpasync16(bs + s1 + 3*BARR*2, pWl0 + rstep + off);
        cpcommit();
    };
    issue(0);

    for (int c = 0; c < nc; c++) {
        if (c + 1 < nc) {
            issue(c + 1);
            asm volatile("cp.async.wait_group 1;");
        } else {
            asm volatile("cp.async.wait_group 0;");
        }
        __syncthreads();
        uint32_t base = sbase + (uint32_t)(c & 1)*(BBUFE*2);
#pragma unroll
        for (int ks = 0; ks < 2; ks++) {
            uint32_t ahf[4][4], alf[4][4], bhf[2][4], blf[2][4];
            int rl = lane & 15, ch = (lane >> 4) * 8;
            int col = ks*16 + ch;
#pragma unroll
            for (int mt=0; mt<4; mt++) {
                int row = wm*64 + mt*16 + rl;
                uint32_t o = (uint32_t)(row*BGS + col)*2;
                ldsm4(base + 0*BARR*2 + o, ahf[mt][0],ahf[mt][1],ahf[mt][2],ahf[mt][3]);
                ldsm4(base + 1*BARR*2 + o, alf[mt][0],alf[mt][1],alf[mt][2],alf[mt][3]);
            }
#pragma unroll
            for (int g=0; g<2; g++) {
                int row = wn*32 + g*16 + rl;
                uint32_t o = (uint32_t)(row*BGS + col)*2;
                ldsm4(base + 2*BARR*2 + o, bhf[g][0],bhf[g][1],bhf[g][2],bhf[g][3]);
                ldsm4(base + 3*BARR*2 + o, blf[g][0],blf[g][1],blf[g][2],blf[g][3]);
            }
#pragma unroll
            for (int mt=0; mt<4; mt++)
#pragma unroll
                for (int g=0; g<2; g++)
#pragma unroll
                    for (int sub=0; sub<2; sub++) {
                        int nt = g*2 + sub;
                        uint32_t h0 = sub ? bhf[g][1] : bhf[g][0];
                        uint32_t h1 = sub ? bhf[g][3] : bhf[g][2];
                        uint32_t l0 = sub ? blf[g][1] : blf[g][0];
                        uint32_t l1 = sub ? blf[g][3] : blf[g][2];
                        mma16816(acc[mt][nt], ahf[mt][0],ahf[mt][1],ahf[mt][2],ahf[mt][3], h0,h1);
                        mma16816(acc[mt][nt], ahf[mt][0],ahf[mt][1],ahf[mt][2],ahf[mt][3], l0,l1);
                        mma16816(acc[mt][nt], alf[mt][0],alf[mt][1],alf[mt][2],alf[mt][3], h0,h1);
                    }
        }
        __syncthreads();
    }

    // epilogue
#pragma unroll
    for (int mt=0; mt<4; mt++)
#pragma unroll
        for (int nt=0; nt<4; nt++) {
            int m0 = bm + wm*64 + mt*16 + (lane >> 2);
            int n0 = bn + wn*32 + nt*8 + (lane & 3)*2;
            float2 bb = make_float2(0.f, 0.f);
            if (EPI != 4 && bias) bb = *(const float2*)(bias + n0);
            float v[4] = {acc[mt][nt][0]+bb.x, acc[mt][nt][1]+bb.y,
                          acc[mt][nt][2]+bb.x, acc[mt][nt][3]+bb.y};
            if (EPI == 4) {
                // cols interleaved (even=w1_j, odd=w3_j); fused swiglu -> col j
                float sA = v[0] / (1.f + __expf(-v[0])) * v[1];
                float sB = v[2] / (1.f + __expf(-v[2])) * v[3];
                int j = n0 >> 1;
                int No = Nn >> 1;
                size_t o0 = (size_t)m0*No + j;
                size_t o1 = (size_t)(m0+8)*No + j;
                float hA = __bfloat162float(__float2bfloat16_rn(sA));
                float hB = __bfloat162float(__float2bfloat16_rn(sB));
                Ch[o0] = __float2bfloat16_rn(hA);
                Cl[o0] = __float2bfloat16_rn(sA - hA);
                Ch[o1] = __float2bfloat16_rn(hB);
                Cl[o1] = __float2bfloat16_rn(sB - hB);
                continue;
            }
            size_t i0 = (size_t)m0*Nn + n0;
            size_t i1 = (size_t)(m0+8)*Nn + n0;
            if (EPI == 3) {
                float h0=__bfloat162float(__float2bfloat16_rn(v[0]));
                float h1=__bfloat162float(__float2bfloat16_rn(v[1]));
                float h2=__bfloat162float(__float2bfloat16_rn(v[2]));
                float h3=__bfloat162float(__float2bfloat16_rn(v[3]));
                *(uint32_t*)(Ch + i0) = packbf(h0, h1);
                *(uint32_t*)(Cl + i0) = packbf(v[0]-h0, v[1]-h1);
                *(uint32_t*)(Ch + i1) = packbf(h2, h3);
                *(uint32_t*)(Cl + i1) = packbf(v[2]-h2, v[3]-h3);
            } else {
                if (EPI >= 1) {
                    float2 r0 = *(const float2*)(resid + i0);
                    float2 r1 = *(const float2*)(resid + i1);
                    v[0]+=r0.x; v[1]+=r0.y; v[2]+=r1.x; v[3]+=r1.y;
                }
                if (EPI == 2) {
                    v[0]=tanhf(v[0]); v[1]=tanhf(v[1]);
                    v[2]=tanhf(v[2]); v[3]=tanhf(v[3]);
                }
                *(float2*)(C + i0) = make_float2(v[0], v[1]);
                *(float2*)(C + i1) = make_float2(v[2], v[3]);
            }
        }
}

// ---------------- mma flash attention: 128q/CTA, kv tiles 64, bf16x3 -------
__global__ __launch_bounds__(256) void attn_mma_kernel(
    const __nv_bfloat16* __restrict__ qh, const __nv_bfloat16* __restrict__ ql,
    __nv_bfloat16* __restrict__ aoh, __nv_bfloat16* __restrict__ aol)
{
    __shared__ __nv_bfloat16 sQ[2][128*40];
    __shared__ __nv_bfloat16 sK[2][64*40];
    __shared__ __nv_bfloat16 sV[2][64*40];
    const int qt = blockIdx.x, h = blockIdx.y, bc = blockIdx.z;
    const int t = threadIdx.x, lane = t & 31, w = t >> 5;
    const size_t tokb = (size_t)bc*NSEQ;
    const float scale = 0.17677669529663687f;

#pragma unroll
    for (int r=0;r<2;r++) {
        int f = t + r*256, row = f >> 2, c8 = (f & 3)*8;
        size_t g = (tokb + qt*128 + row)*HID + h*DHEAD + c8;
        *(uint4*)&sQ[0][row*40+c8] = *(const uint4*)(qh + g);
        *(uint4*)&sQ[1][row*40+c8] = *(const uint4*)(ql + g);
    }
    __syncthreads();

    uint32_t qfh[2][4], qfl[2][4];
    {
        const uint32_t q0 = smem_u32(sQ[0]), q1 = smem_u32(sQ[1]);
#pragma unroll
        for (int kc=0;kc<2;kc++) {
            int row = w*16 + (lane & 15), col = kc*16 + (lane >> 4)*8;
            uint32_t o2 = (uint32_t)(row*40 + col)*2;
            ldsm4(q0 + o2, qfh[kc][0],qfh[kc][1],qfh[kc][2],qfh[kc][3]);
            ldsm4(q1 + o2, qfl[kc][0],qfl[kc][1],qfl[kc][2],qfl[kc][3]);
        }
    }

    float o[4][4];
#pragma unroll
    for (int i=0;i<4;i++)
#pragma unroll
        for (int j=0;j<4;j++) o[i][j]=0.f;
    float mrun0=-1e30f, mrun1=-1e30f, lrun0=0.f, lrun1=0.f;
    const uint32_t k0b = smem_u32(sK[0]), k1b = smem_u32(sK[1]);
    const uint32_t v0b = smem_u32(sV[0]), v1b = smem_u32(sV[1]);

    for (int kt=0; kt<16; kt++) {
        __syncthreads();
        {
            int row = t >> 2, c8 = (t & 3)*8;
            size_t g = (tokb + kt*64 + row)*HID + h*DHEAD + c8;
            *(uint4*)&sK[0][row*40+c8] = *(const uint4*)(qh + g + DMODEL);
            *(uint4*)&sK[1][row*40+c8] = *(const uint4*)(ql + g + DMODEL);
            *(uint4*)&sV[0][row*40+c8] = *(const uint4*)(qh + g + 2*DMODEL);
            *(uint4*)&sV[1][row*40+c8] = *(const uint4*)(ql + g + 2*DMODEL);
        }
        __syncthreads();

        float S[8][4];
#pragma unroll
        for (int j=0;j<8;j++)
#pragma unroll
            for (int e=0;e<4;e++) S[j][e]=0.f;
#pragma unroll
        for (int kc=0;kc<2;kc++)
#pragma unroll
            for (int jp=0;jp<4;jp++) {
                int row = jp*16 + ((lane>>4)&1)*8 + (lane&7);
                int col = kc*16 + ((lane>>3)&1)*8;
                uint32_t o2 = (uint32_t)(row*40 + col)*2;
                uint32_t h0,h1,h2,h3, l0,l1,l2,l3;
                ldsm4(k0b + o2, h0,h1,h2,h3);
                ldsm4(k1b + o2, l0,l1,l2,l3);
                mma16816(S[2*jp],   qfh[kc][0],qfh[kc][1],qfh[kc][2],qfh[kc][3], h0,h1);
                mma16816(S[2*jp+1], qfh[kc][0],qfh[kc][1],qfh[kc][2],qfh[kc][3], h2,h3);
                mma16816(S[2*jp],   qfh[kc][0],qfh[kc][1],qfh[kc][2],qfh[kc][3], l0,l1);
                mma16816(S[2*jp+1], qfh[kc][0],qfh[kc][1],qfh[kc][2],qfh[kc][3], l2,l3);
                mma16816(S[2*jp],   qfl[kc][0],qfl[kc][1],qfl[kc][2],qfl[kc][3], h0,h1);
                mma16816(S[2*jp+1], qfl[kc][0],qfl[kc][1],qfl[kc][2],qfl[kc][3], h2,h3);
            }

        float mx0=-1e30f, mx1=-1e30f;
#pragma unroll
        for (int j=0;j<8;j++) {
            mx0 = fmaxf(mx0, fmaxf(S[j][0], S[j][1]));
            mx1 = fmaxf(mx1, fmaxf(S[j][2], S[j][3]));
        }
        mx0 *= scale; mx1 *= scale;
        mx0 = fmaxf(mx0, __shfl_xor_sync(0xffffffffu, mx0, 1));
        mx0 = fmaxf(mx0, __shfl_xor_sync(0xffffffffu, mx0, 2));
        mx1 = fmaxf(mx1, __shfl_xor_sync(0xffffffffu, mx1, 1));
        mx1 = fmaxf(mx1, __shfl_xor_sync(0xffffffffu, mx1, 2));
        float mn0 = fmaxf(mrun0, mx0), mn1 = fmaxf(mrun1, mx1);
        float a0 = __expf(mrun0 - mn0), a1 = __expf(mrun1 - mn1);
        mrun0 = mn0; mrun1 = mn1;
#pragma unroll
        for (int nt=0;nt<4;nt++) {
            o[nt][0]*=a0; o[nt][1]*=a0; o[nt][2]*=a1; o[nt][3]*=a1;
        }
        float rs0=0.f, rs1=0.f;
#pragma unroll
        for (int kc2=0;kc2<4;kc2++) {
            int j0 = 2*kc2;
            float p00=__expf(S[j0][0]*scale - mn0), p01=__expf(S[j0][1]*scale - mn0);
            float p02=__expf(S[j0][2]*scale - mn1), p03=__expf(S[j0][3]*scale - mn1);
            float p10=__expf(S[j0+1][0]*scale - mn0), p11=__expf(S[j0+1][1]*scale - mn0);
            float p12=__expf(S[j0+1][2]*scale - mn1), p13=__expf(S[j0+1][3]*scale - mn1);
            rs0 += p00+p01+p10+p11;
            rs1 += p02+p03+p12+p13;
            float q00=__bfloat162float(__float2bfloat16_rn(p00));
            float q01=__bfloat162float(__float2bfloat16_rn(p01));
            float q02=__bfloat162float(__float2bfloat16_rn(p02));
            float q03=__bfloat162float(__float2bfloat16_rn(p03));
            float q10=__bfloat162float(__float2bfloat16_rn(p10));
            float q11=__bfloat162float(__float2bfloat16_rn(p11));
            float q12=__bfloat162float(__float2bfloat16_rn(p12));
            float q13=__bfloat162float(__float2bfloat16_rn(p13));
            uint32_t aph[4] = {packbf(q00,q01), packbf(q02,q03),
                               packbf(q10,q11), packbf(q12,q13)};
            uint32_t apl[4] = {packbf(p00-q00,p01-q01), packbf(p02-q02,p03-q03),
                               packbf(p10-q10,p11-q11), packbf(p12-q12,p13-q13)};
#pragma unroll
            for (int g=0; g<2; g++) {
                int row = kc2*16 + ((lane>>3)&1)*8 + (lane&7);
                int col = g*16 + ((lane>>4)&1)*8;
                uint32_t o2 = (uint32_t)(row*40 + col)*2;
                uint32_t vh0,vh1,vh2,vh3, vl0,vl1,vl2,vl3;
                ldsm4t(v0b + o2, vh0,vh1,vh2,vh3);
                ldsm4t(v1b + o2, vl0,vl1,vl2,vl3);
                mma16816(o[2*g],   aph[0],aph[1],aph[2],aph[3], vh0,vh1);
                mma16816(o[2*g+1], aph[0],aph[1],aph[2],aph[3], vh2,vh3);
                mma16816(o[2*g],   aph[0],aph[1],aph[2],aph[3], vl0,vl1);
                mma16816(o[2*g+1], aph[0],aph[1],aph[2],aph[3], vl2,vl3);
                mma16816(o[2*g],   apl[0],apl[1],apl[2],apl[3], vh0,vh1);
                mma16816(o[2*g+1], apl[0],apl[1],apl[2],apl[3], vh2,vh3);
            }
        }
        rs0 += __shfl_xor_sync(0xffffffffu, rs0, 1);
        rs0 += __shfl_xor_sync(0xffffffffu, rs0, 2);
        rs1 += __shfl_xor_sync(0xffffffffu, rs1, 1);
        rs1 += __shfl_xor_sync(0xffffffffu, rs1, 2);
        lrun0 = lrun0*a0 + rs0;
        lrun1 = lrun1*a1 + rs1;
    }

    float inv0 = 1.f/lrun0, inv1 = 1.f/lrun1;
    int r0 = qt*128 + w*16 + (lane >> 2);
#pragma unroll
    for (int nt=0; nt<4; nt++) {
        int d = h*DHEAD + nt*8 + (lane & 3)*2;
        size_t i0 = (tokb + r0)*DMODEL + d;
        size_t i1 = (tokb + r0 + 8)*DMODEL + d;
        float v0 = o[nt][0]*inv0, v1 = o[nt][1]*inv0;
        float v2 = o[nt][2]*inv1, v3 = o[nt][3]*inv1;
        float h0=__bfloat162float(__float2bfloat16_rn(v0));
        float h1=__bfloat162float(__float2bfloat16_rn(v1));
        float h2=__bfloat162float(__float2bfloat16_rn(v2));
        float h3=__bfloat162float(__float2bfloat16_rn(v3));
        *(uint32_t*)(aoh + i0) = packbf(h0, h1);
        *(uint32_t*)(aol + i0) = packbf(v0-h0, v1-h1);
        *(uint32_t*)(aoh + i1) = packbf(h2, h3);
        *(uint32_t*)(aol + i1) = packbf(v2-h2, v3-h3);
    }
}

// ---------------- RMS norm ----------------
__global__ __launch_bounds__(256) void rms_kernel(
    const float* __restrict__ x, const float* __restrict__ w,
    __nv_bfloat16* __restrict__ yh, __nv_bfloat16* __restrict__ yl)
{
    int tok  = blockIdx.x*8 + (threadIdx.x >> 5);
    int lane = threadIdx.x & 31;
    const float* xp = x + (size_t)tok*DMODEL;
    float4 a = *(const float4*)(xp + lane*4);
    float4 b = *(const float4*)(xp + 128 + lane*4);
    float ss = a.x*a.x + a.y*a.y + a.z*a.z + a.w*a.w
             + b.x*b.x + b.y*b.y + b.z*b.z + b.w*b.w;
#pragma unroll
    for (int off=16; off; off>>=1) ss += __shfl_xor_sync(0xffffffffu, ss, off);
    float r = rsqrtf(ss*(1.0f/DMODEL) + 1e-5f);
    float4 wa = *(const float4*)(w + lane*4);
    float4 wb = *(const float4*)(w + 128 + lane*4);
    float va[8] = {a.x*r*wa.x, a.y*r*wa.y, a.z*r*wa.z, a.w*r*wa.w,
                   b.x*r*wb.x, b.y*r*wb.y, b.z*r*wb.z, b.w*r*wb.w};
    size_t o0 = (size_t)tok*DMODEL + lane*4;
    size_t o1 = o0 + 128;
    float h[8];
#pragma unroll
    for (int i=0;i<8;i++) h[i] = __bfloat162float(__float2bfloat16_rn(va[i]));
    *(uint2*)(yh + o0) = make_uint2(packbf(h[0],h[1]), packbf(h[2],h[3]));
    *(uint2*)(yh + o1) = make_uint2(packbf(h[4],h[5]), packbf(h[6],h[7]));
    *(uint2*)(yl + o0) = make_uint2(packbf(va[0]-h[0],va[1]-h[1]), packbf(va[2]-h[2],va[3]-h[3]));
    *(uint2*)(yl + o1) = make_uint2(packbf(va[4]-h[4],va[5]-h[5]), packbf(va[6]-h[6],va[7]-h[7]));
}

// ---------------- edge bucketing ----------------
__global__ void bucket_kernel(const int* __restrict__ w)
{
    __shared__ int s_dst[NEDGE];
    __shared__ int s_is64;
    __shared__ int s_cnt[LLOG];
    __shared__ int s_st[LLOG+1];
    int t = threadIdx.x;
    if (t == 0) {
        int z = 0;
        for (int i=1;i<64;i+=2) z |= w[i];
        s_is64 = (z == 0);
    }
    __syncthreads();
    int is64 = s_is64;
    for (int e=t; e<NEDGE; e+=256)
        s_dst[e] = is64 ? w[2*NEDGE + 2*e] : w[NEDGE + e];
    __syncthreads();
    int cnt = 0;
    for (int e=0;e<NEDGE;e++) cnt += (s_dst[e] == t);
    s_cnt[t] = cnt;
    __syncthreads();
    if (t == 0) {
        int acc = 0;
        for (int l=0;l<LLOG;l++) { s_st[l] = acc; acc += s_cnt[l]; }
        s_st[LLOG] = acc;
    }
    __syncthreads();
    g_start[t] = s_st[t];
    if (t == 0) g_start[LLOG] = s_st[LLOG];
    int idx = s_st[t];
    for (int e=0;e<NEDGE;e++) {
        if (s_dst[e] == t) {
            int src = is64 ? w[2*e] : w[e];
            g_order[idx++] = src;
        }
    }
}

// ---------------- scatter-multiply ----------------
__global__ __launch_bounds__(256) void scatterprod_kernel(
    const float* __restrict__ x3, float* __restrict__ lout)
{
    int l = blockIdx.x, bc = blockIdx.y, d = threadIdx.x;
    int s = g_start[l], e = g_start[l+1];
    float p = 1.f;
    const float* base = x3 + (size_t)bc*NSEQ*DMODEL + d;
    for (int i=s; i<e; i++) p *= base[(size_t)g_order[i]*DMODEL];
    lout[((size_t)bc*LLOG + l)*DMODEL + d] = p;
}

// ---------------- head ----------------
__global__ __launch_bounds__(256) void head_kernel(
    const float* __restrict__ l2, const float* __restrict__ hw,
    const float* __restrict__ hb, float* __restrict__ out)
{
    int tok  = blockIdx.x*8 + (threadIdx.x >> 5);
    int lane = threadIdx.x & 31;
    const float* p = l2 + (size_t)tok*DMODEL;
    float s = 0.f;
#pragma unroll
    for (int i=0;i<8;i++) s += p[lane + 32*i]*hw[lane + 32*i];
#pragma unroll
    for (int off=16; off; off>>=1) s += __shfl_xor_sync(0xffffffffu, s, off);
    if (lane == 0) out[tok] = s + hb[0];
}

// ---------------- host orchestration ----------------
// weight offsets (elements) in g_whi/g_wlo
#define WO_INPROJ 0         // 768x256
#define WO_OUT    196608    // 256x256
#define WO_FW2    262144    // 256x768
#define WO_DW2    458752    // 256x768
#define WO_LW2    655360    // 256x768
#define WO_F13    851968    // 1536x256 interleaved w1/w3
#define WO_D13    1245184
#define WO_L13    1638400

static __nv_bfloat16 *h_whi, *h_wlo;

static inline void launch_bgemm(int epi, const __nv_bfloat16* Ah, const __nv_bfloat16* Al,
                                size_t woff, const float* bias, const float* resid,
                                float* C, __nv_bfloat16* Ch, __nv_bfloat16* Cl,
                                int M, int Nn, int K)
{
    dim3 grid(Nn/128, M/128);
    const __nv_bfloat16* Wh = h_whi + woff;
    const __nv_bfloat16* Wl = h_wlo + woff;
    if (epi == 0) {
        cudaFuncSetAttribute(bgemm_kernel<0>, cudaFuncAttributeMaxDynamicSharedMemorySize, BG_SMEM);
        bgemm_kernel<0><<<grid,256,BG_SMEM>>>(Ah,Al,Wh,Wl,bias,resid,C,Ch,Cl,M,Nn,K);
    } else if (epi == 1) {
        cudaFuncSetAttribute(bgemm_kernel<1>, cudaFuncAttributeMaxDynamicSharedMemorySize, BG_SMEM);
        bgemm_kernel<1><<<grid,256,BG_SMEM>>>(Ah,Al,Wh,Wl,bias,resid,C,Ch,Cl,M,Nn,K);
    } else if (epi == 2) {
        cudaFuncSetAttribute(bgemm_kernel<2>, cudaFuncAttributeMaxDynamicSharedMemorySize, BG_SMEM);
        bgemm_kernel<2><<<grid,256,BG_SMEM>>>(Ah,Al,Wh,Wl,bias,resid,C,Ch,Cl,M,Nn,K);
    } else if (epi == 3) {
        cudaFuncSetAttribute(bgemm_kernel<3>, cudaFuncAttributeMaxDynamicSharedMemorySize, BG_SMEM);
        bgemm_kernel<3><<<grid,256,BG_SMEM>>>(Ah,Al,Wh,Wl,bias,resid,C,Ch,Cl,M,Nn,K);
    } else {
        cudaFuncSetAttribute(bgemm_kernel<4>, cudaFuncAttributeMaxDynamicSharedMemorySize, BG_SMEM);
        bgemm_kernel<4><<<grid,256,BG_SMEM>>>(Ah,Al,Wh,Wl,bias,resid,C,Ch,Cl,M,Nn,K);
    }
}

extern "C" void kernel_launch(void* const* d_in, const int* in_sizes, int n_in,
                              void* d_out, int out_size)
{
    (void)in_sizes; (void)n_in; (void)out_size;
    const float* v           = (const float*)d_in[0];
    const int*   d2l         = (const int*)  d_in[1];
    const float* attn_norm_w = (const float*)d_in[2];
    const float* in_proj_w   = (const float*)d_in[3];
    const float* in_proj_b   = (const float*)d_in[4];
    const float* out_w       = (const float*)d_in[5];
    const float* out_b       = (const float*)d_in[6];
    const float* ffn_norm_w  = (const float*)d_in[7];
    const float* ffn_w1      = (const float*)d_in[8];
    const float* ffn_w2      = (const float*)d_in[9];
    const float* ffn_w3      = (const float*)d_in[10];
    const float* du_norm_w   = (const float*)d_in[11];
    const float* du_w1       = (const float*)d_in[12];
    const float* du_w2       = (const float*)d_in[13];
    const float* du_w3       = (const float*)d_in[14];
    const float* lu_norm_w   = (const float*)d_in[15];
    const float* lu_w1       = (const float*)d_in[16];
    const float* lu_w2       = (const float*)d_in[17];
    const float* lu_w3       = (const float*)d_in[18];
    const float* head_w      = (const float*)d_in[19];
    const float* head_b      = (const float*)d_in[20];
    float* out = (float*)d_out;

    float *a, *x2, *x3, *lb, *l2;
    __nv_bfloat16 *xnh, *xnl, *qkvh, *qkvl, *t1h, *t1l, *aoh, *aol;
    cudaGetSymbolAddress((void**)&a,    g_a);
    cudaGetSymbolAddress((void**)&x2,   g_x2);
    cudaGetSymbolAddress((void**)&x3,   g_x3);
    cudaGetSymbolAddress((void**)&lb,   g_l);
    cudaGetSymbolAddress((void**)&l2,   g_l2);
    cudaGetSymbolAddress((void**)&xnh,  g_xnh);
    cudaGetSymbolAddress((void**)&xnl,  g_xnl);
    cudaGetSymbolAddress((void**)&qkvh, g_qkvh);
    cudaGetSymbolAddress((void**)&qkvl, g_qkvl);
    cudaGetSymbolAddress((void**)&t1h,  g_t1h);
    cudaGetSymbolAddress((void**)&t1l,  g_t1l);
    cudaGetSymbolAddress((void**)&aoh,  g_aoh);
    cudaGetSymbolAddress((void**)&aol,  g_aol);
    cudaGetSymbolAddress((void**)&h_whi, g_whi);
    cudaGetSymbolAddress((void**)&h_wlo, g_wlo);

    // 0) weight splits: flat regions + 3 interleaved w1/w3 pairs
    wconv_all_kernel<<<(212992+255)/256,256>>>(
        in_proj_w, out_w, ffn_w2, du_w2, lu_w2, h_whi, h_wlo);
    wconv_pair_kernel<<<384,256>>>(ffn_w1, ffn_w3, h_whi+WO_F13, h_wlo+WO_F13);
    wconv_pair_kernel<<<384,256>>>(du_w1,  du_w3,  h_whi+WO_D13, h_wlo+WO_D13);
    wconv_pair_kernel<<<384,256>>>(lu_w1,  lu_w3,  h_whi+WO_L13, h_wlo+WO_L13);
    bucket_kernel<<<1,256>>>(d2l);

    // 1) attn pre-norm
    rms_kernel<<<NTOK/8,256>>>(v, attn_norm_w, xnh, xnl);
    // 2) qkv projection
    launch_bgemm(3, xnh, xnl, WO_INPROJ, in_proj_b, nullptr, nullptr, qkvh, qkvl, NTOK, HID, DMODEL);
    // 3) attention
    { dim3 g(NSEQ/128, NHEAD, BC); attn_mma_kernel<<<g,256>>>(qkvh, qkvl, aoh, aol); }
    // 4) out projection + residual v -> a
    launch_bgemm(1, aoh, aol, WO_OUT, out_b, v, a, nullptr, nullptr, NTOK, DMODEL, DMODEL);
    // 5) FFN: fused w1/w3+swiglu, then w2
    rms_kernel<<<NTOK/8,256>>>(a, ffn_norm_w, xnh, xnl);
    launch_bgemm(4, xnh, xnl, WO_F13, nullptr, nullptr, nullptr, t1h, t1l, NTOK, 2*HID, DMODEL);
    launch_bgemm(1, t1h, t1l, WO_FW2, nullptr, a, x2, nullptr, nullptr, NTOK, DMODEL, HID);
    // 6) du block with tanh
    rms_kernel<<<NTOK/8,256>>>(x2, du_norm_w, xnh, xnl);
    launch_bgemm(4, xnh, xnl, WO_D13, nullptr, nullptr, nullptr, t1h, t1l, NTOK, 2*HID, DMODEL);
    launch_bgemm(2, t1h, t1l, WO_DW2, nullptr, x2, x3, nullptr, nullptr, NTOK, DMODEL, HID);
    // 7) scatter-multiply
    { dim3 g(LLOG, BC); scatterprod_kernel<<<g,256>>>(x3, lb); }
    // 8) lu block
    rms_kernel<<<NTOKL/8,256>>>(lb, lu_norm_w, xnh, xnl);
    launch_bgemm(4, xnh, xnl, WO_L13, nullptr, nullptr, nullptr, t1h, t1l, NTOKL, 2*HID, DMODEL);
    launch_bgemm(1, t1h, t1l, WO_LW2, nullptr, lb, l2, nullptr, nullptr, NTOKL, DMODEL, HID);
    // 9) head
    head_kernel<<<NTOKL/8,256>>>(l2, head_w, head_b, out);
}